// round 5
// baseline (speedup 1.0000x reference)
#include <cuda_runtime.h>
#include <stdint.h>

#define BB   32
#define CC   256
#define HH   56
#define WWID 56
#define OO   512
#define HW   (HH*WWID)      // 3136
#define CKK  (CC*9)         // 2304
#define NPIX (BB*HW)        // 100352

#define BM 128
#define BN 128
#define BK 8
#define TM 8
#define TN 8

// Ternary weight materialized as fp32, laid out [o][k] row-major for coalesced
// tile loads. 512*2304*4 B = 4.7 MB static device scratch (no allocations).
__device__ float g_wt[OO * CKK];

__global__ void prep_weights(const int* __restrict__ pos,
                             const int* __restrict__ neg) {
    int i = blockIdx.x * blockDim.x + threadIdx.x;   // over CKK*OO, [k][o] layout
    if (i < OO * CKK) {
        int k = i / OO;
        int o = i - k * OO;
        g_wt[o * CKK + k] = (float)pos[i] - (float)neg[i];
    }
}

__global__ __launch_bounds__(256, 2)
void conv_gemm(const float* __restrict__ x, float* __restrict__ out) {
    __shared__ float As[BK][BM];   // [k][o]
    __shared__ float Bs[BK][BN];   // [k][n]

    const int tid = threadIdx.x;
    const int bm  = blockIdx.y;    // 0..3   (output-channel tile)
    const int bn  = blockIdx.x;    // 0..783 (pixel tile)

    // ---- A loader: one float4 along k per thread ----
    const int aRow = tid >> 1;            // 0..127 : o within tile
    const int aCol = (tid & 1) << 2;      // 0 or 4 : k offset
    const float* Aptr = g_wt + (size_t)(bm * BM + aRow) * CKK;

    // ---- B loader: 4 scalar gathers (fixed pixel, 4 k's) per thread ----
    const int bCol  = tid & 127;          // n within tile
    const int bRow0 = (tid >> 7) << 2;    // 0 or 4
    const int n  = bn * BN + bCol;        // global pixel id (always < NPIX)
    const int b  = n / HW;
    const int hw = n - b * HW;
    const int h  = hw / WWID;
    const int w  = hw - h * WWID;
    const float* xb = x + (size_t)b * CC * HW;

    // ---- compute mapping: 16x16 threads, each 8x8 outputs ----
    const int tx = tid & 15;
    const int ty = tid >> 4;

    float acc[TM][TN];
#pragma unroll
    for (int i = 0; i < TM; i++)
#pragma unroll
        for (int j = 0; j < TN; j++) acc[i][j] = 0.f;

    for (int k0 = 0; k0 < CKK; k0 += BK) {
        // stage A (transposed into [k][o])
        float4 av = *reinterpret_cast<const float4*>(Aptr + k0 + aCol);
        As[aCol + 0][aRow] = av.x;
        As[aCol + 1][aRow] = av.y;
        As[aCol + 2][aRow] = av.z;
        As[aCol + 3][aRow] = av.w;

        // stage B (implicit im2col gather with border predication)
#pragma unroll
        for (int r = 0; r < 4; r++) {
            int k  = k0 + bRow0 + r;
            int c  = k / 9;
            int t  = k - c * 9;
            int kh = t / 3;
            int kw = t - kh * 3;
            int hh = h + kh - 1;
            int ww = w + kw - 1;
            float v = 0.f;
            if ((unsigned)hh < (unsigned)HH && (unsigned)ww < (unsigned)WWID)
                v = xb[c * HW + hh * WWID + ww];
            Bs[bRow0 + r][bCol] = v;
        }
        __syncthreads();

#pragma unroll
        for (int kk = 0; kk < BK; kk++) {
            float af[TM], bf[TN];
#pragma unroll
            for (int i = 0; i < TM; i++) af[i] = As[kk][ty * TM + i];
#pragma unroll
            for (int j = 0; j < TN; j++) bf[j] = Bs[kk][tx * TN + j];
#pragma unroll
            for (int i = 0; i < TM; i++)
#pragma unroll
                for (int j = 0; j < TN; j++)
                    acc[i][j] += af[i] * bf[j];
        }
        __syncthreads();
    }

    // ---- epilogue: out[(b*OO + o)*HW + hw] ----
#pragma unroll
    for (int i = 0; i < TM; i++) {
        int o = bm * BM + ty * TM + i;
#pragma unroll
        for (int j = 0; j < TN; j++) {
            int nn  = bn * BN + tx * TN + j;
            int b2  = nn / HW;
            int hw2 = nn - b2 * HW;
            out[((size_t)b2 * OO + o) * HW + hw2] = acc[i][j];
        }
    }
}

extern "C" void kernel_launch(void* const* d_in, const int* in_sizes, int n_in,
                              void* d_out, int out_size) {
    const float* x   = (const float*)d_in[0];
    const int*   pos = (const int*)d_in[1];
    const int*   neg = (const int*)d_in[2];
    float*       out = (float*)d_out;

    prep_weights<<<(OO * CKK + 255) / 256, 256>>>(pos, neg);

    dim3 grid(NPIX / BN, OO / BM);   // 784 x 4
    conv_gemm<<<grid, 256>>>(x, out);
}

// round 7
// speedup vs baseline: 2.5602x; 2.5602x over previous
#include <cuda_runtime.h>
#include <stdint.h>

#define BB   32
#define CC   256
#define HH   56
#define WW_  56
#define OO   512
#define HW   (HH*WW_)        // 3136
#define CHW  (CC*HW)         // 802816
#define CKK  (CC*9)          // 2304
#define NPIX (BB*HW)         // 100352

#define BM 128
#define BN 256
#define BK 32
#define NCH (CKK/BK)         // 72
#define NT  512              // threads per CTA

#define A_STRIDE 36          // floats per A row (32 + 4 pad)  -> frag LDS conflict-free
#define B_STRIDE 264         // floats per B row (256 + 8 pad) -> frag LDS conflict-free
#define A_BYTES (BM*A_STRIDE*4)          // 18432
#define B_BYTES (BK*B_STRIDE*4)          // 33792
#define SMEM_BYTES (2*A_BYTES + 2*B_BYTES)  // 104448

// -------- static device scratch (no allocations) --------
__device__ float g_wt[OO * CKK];      // ternary weights, fp32 [o][k], exact in tf32
__device__ float g_xc[BB * CHW];      // x pre-rounded to tf32 (rna), 103 MB

// -------- helpers --------
__device__ __forceinline__ uint32_t smem_u32(const void* p) {
    uint32_t a;
    asm("{ .reg .u64 t; cvta.to.shared.u64 t, %1; cvt.u32.u64 %0, t; }" : "=r"(a) : "l"(p));
    return a;
}
__device__ __forceinline__ float to_tf32(float v) {
    uint32_t r;
    asm("cvt.rna.tf32.f32 %0, %1;" : "=r"(r) : "f"(v));
    return __uint_as_float(r);
}
__device__ __forceinline__ void cp16(uint32_t dst, const void* src) {
    asm volatile("cp.async.cg.shared.global [%0], [%1], 16;" :: "r"(dst), "l"(src) : "memory");
}
// src-size form: sz=4 copies, sz=0 zero-fills (conv border)
__device__ __forceinline__ void cp4(uint32_t dst, const void* src, uint32_t sz) {
    asm volatile("cp.async.ca.shared.global [%0], [%1], 4, %2;" :: "r"(dst), "l"(src), "r"(sz) : "memory");
}
__device__ __forceinline__ void mma8(float* c, const uint32_t* a, const uint32_t* b) {
    asm volatile(
        "mma.sync.aligned.m16n8k8.row.col.f32.tf32.tf32.f32 "
        "{%0,%1,%2,%3}, {%4,%5,%6,%7}, {%8,%9}, {%0,%1,%2,%3};"
        : "+f"(c[0]), "+f"(c[1]), "+f"(c[2]), "+f"(c[3])
        : "r"(a[0]), "r"(a[1]), "r"(a[2]), "r"(a[3]), "r"(b[0]), "r"(b[1]));
}

// -------- prep kernels --------
__global__ void prep_weights(const int* __restrict__ pos, const int* __restrict__ neg) {
    int i = blockIdx.x * blockDim.x + threadIdx.x;   // over [k][o] input layout
    if (i < OO * CKK) {
        int k = i / OO;
        int o = i - k * OO;
        g_wt[o * CKK + k] = (float)(pos[i] - neg[i]);
    }
}
__global__ void prep_x(const float4* __restrict__ x) {
    int i = blockIdx.x * blockDim.x + threadIdx.x;
    if (i < BB * CHW / 4) {
        float4 v = x[i];
        v.x = to_tf32(v.x); v.y = to_tf32(v.y);
        v.z = to_tf32(v.z); v.w = to_tf32(v.w);
        reinterpret_cast<float4*>(g_xc)[i] = v;
    }
}

// -------- main kernel: implicit-im2col GEMM on mma.sync tf32 --------
__global__ void __launch_bounds__(NT)
conv_mma(float* __restrict__ out) {
    extern __shared__ char sm[];
    const uint32_t smb = smem_u32(sm);
    const int tid  = threadIdx.x;
    const int bn   = blockIdx.x;           // 0..391 pixel tile
    const int bm   = blockIdx.y;           // 0..3   o tile
    const int lane = tid & 31, wid = tid >> 5;
    const int wm   = wid & 3;              // m strip (32 rows)
    const int wn   = wid >> 2;             // n strip (64 cols)

    // ---- per-thread gather identity: fixed pixel, 16 k's per chunk ----
    const int px  = tid & 255;
    const int kh2 = (tid >> 8) * 16;       // 0 or 16
    const int n   = bn * BN + px;
    const int b   = n / HW;
    const int hw  = n - b * HW;
    const int h0  = hw / WW_ - 1;
    const int w0  = hw - (h0 + 1) * WW_ - 1;
    const float* xb = g_xc + (size_t)b * CHW + h0 * WW_ + w0;

    const float* Ab = g_wt + (size_t)(bm * BM) * CKK;

    float acc[2][8][4];
#pragma unroll
    for (int i = 0; i < 2; i++)
#pragma unroll
        for (int j = 0; j < 8; j++)
#pragma unroll
            for (int q = 0; q < 4; q++) acc[i][j][q] = 0.f;

    // ---- stage: cp.async one K-chunk (A tile + im2col B tile) ----
#define STAGE(CH, BUF) do {                                                     \
        const int k0 = (CH) * BK;                                               \
        const uint32_t abase = smb + (BUF) * A_BYTES;                           \
        _Pragma("unroll")                                                       \
        for (int i = 0; i < 2; i++) {                                           \
            int u = tid + i * 512;                                              \
            int row = u >> 3, kc = (u & 7) * 4;                                 \
            cp16(abase + row * (A_STRIDE*4) + kc * 4,                           \
                 Ab + (size_t)row * CKK + k0 + kc);                             \
        }                                                                       \
        const uint32_t bbase = smb + 2*A_BYTES + (BUF) * B_BYTES + px * 4;      \
        _Pragma("unroll")                                                       \
        for (int j = 0; j < 16; j++) {                                          \
            int k  = k0 + kh2 + j;                                              \
            int c  = k / 9;                                                     \
            int t  = k - c * 9;                                                 \
            int dh = t / 3;                                                     \
            int dw = t - dh * 3;                                                \
            unsigned ok = ((unsigned)(h0 + dh) < HH) & ((unsigned)(w0 + dw) < WW_); \
            const float* src = xb + c * HW + dh * WW_ + dw;                     \
            cp4(bbase + (kh2 + j) * (B_STRIDE*4), ok ? src : g_xc, ok ? 4u : 0u); \
        }                                                                       \
        asm volatile("cp.async.commit_group;" ::: "memory");                    \
    } while (0)

    STAGE(0, 0);
    STAGE(1, 1);

    const int fr = lane >> 2;   // fragment row group
    const int fc = lane & 3;    // fragment k/col group

    for (int ch = 0; ch < NCH; ch++) {
        if (ch < NCH - 1) asm volatile("cp.async.wait_group 1;" ::: "memory");
        else              asm volatile("cp.async.wait_group 0;" ::: "memory");
        __syncthreads();

        const int buf = ch & 1;
        const uint32_t* As = reinterpret_cast<const uint32_t*>(sm + buf * A_BYTES);
        const uint32_t* Bs = reinterpret_cast<const uint32_t*>(sm + 2*A_BYTES + buf * B_BYTES);

#pragma unroll
        for (int ks = 0; ks < 4; ks++) {
            const int kb = ks * 8;
            uint32_t af[2][4];
#pragma unroll
            for (int mt = 0; mt < 2; mt++) {
                int rowA = wm * 32 + mt * 16 + fr;
                af[mt][0] = As[rowA * A_STRIDE + kb + fc];
                af[mt][1] = As[(rowA + 8) * A_STRIDE + kb + fc];
                af[mt][2] = As[rowA * A_STRIDE + kb + fc + 4];
                af[mt][3] = As[(rowA + 8) * A_STRIDE + kb + fc + 4];
            }
            const int ncol = wn * 64 + fr;
#pragma unroll
            for (int nt = 0; nt < 8; nt++) {
                uint32_t bf[2];
                bf[0] = Bs[(kb + fc) * B_STRIDE + ncol + nt * 8];
                bf[1] = Bs[(kb + fc + 4) * B_STRIDE + ncol + nt * 8];
                mma8(acc[0][nt], af[0], bf);
                mma8(acc[1][nt], af[1], bf);
            }
        }
        __syncthreads();
        if (ch + 2 < NCH) STAGE(ch + 2, buf);
    }

    // ---- epilogue: direct register -> gmem scatter (32B-sector packed) ----
#pragma unroll
    for (int nt = 0; nt < 8; nt++) {
#pragma unroll
        for (int e = 0; e < 2; e++) {
            int col = wn * 64 + nt * 8 + fc * 2 + e;
            int nn  = bn * BN + col;
            int b2  = nn / HW;
            int hw2 = nn - b2 * HW;
            float* po = out + (size_t)b2 * OO * HW
                            + (size_t)(bm * BM + wm * 32) * HW + hw2;
#pragma unroll
            for (int mt = 0; mt < 2; mt++)
#pragma unroll
                for (int hr = 0; hr < 2; hr++)
                    po[(mt * 16 + fr + hr * 8) * HW] = acc[mt][nt][hr * 2 + e];
        }
    }
#undef STAGE
}

extern "C" void kernel_launch(void* const* d_in, const int* in_sizes, int n_in,
                              void* d_out, int out_size) {
    const float* x   = (const float*)d_in[0];
    const int*   pos = (const int*)d_in[1];
    const int*   neg = (const int*)d_in[2];
    float*       out = (float*)d_out;

    cudaFuncSetAttribute(conv_mma, cudaFuncAttributeMaxDynamicSharedMemorySize, SMEM_BYTES);

    prep_weights<<<(OO * CKK + 255) / 256, 256>>>(pos, neg);
    prep_x<<<(BB * CHW / 4 + 255) / 256, 256>>>((const float4*)x);

    dim3 grid(NPIX / BN, OO / BM);   // 392 x 4
    conv_mma<<<grid, NT, SMEM_BYTES>>>(out);
}

// round 11
// speedup vs baseline: 4.3111x; 1.6839x over previous
#include <cuda_runtime.h>
#include <cuda_fp16.h>
#include <stdint.h>

#define BB   32
#define CC   256
#define HH   56
#define WW_  56
#define OO   512
#define HW   (HH*WW_)        // 3136
#define CHW  (CC*HW)         // 802816
#define CKK  (CC*9)          // 2304
#define NPIX (BB*HW)         // 100352

#define BM 128
#define BN 256
#define BK 32
#define NCH (CKK/BK)         // 72
#define NT  512

#define KPAD 40              // halves per smem row (32 + 8 pad) = 80 B
#define A_BYTES (BM*KPAD*2)  // 10240
#define B_BYTES (BN*KPAD*2)  // 20480
#define OFF_TAB 0
#define OFF_A   9216
#define OFF_B   (OFF_A + 2*A_BYTES)        // 29696
#define SMEM_BYTES (OFF_B + 2*B_BYTES)     // 70656
#define EPI_STRIDE 261

// -------- static device scratch --------
__device__ __align__(16) uint16_t g_wth[OO * CKK];   // ternary weights as fp16 (exact)
__device__ __align__(16) uint16_t g_xh[BB * CHW];    // x as fp16
__device__ uint32_t g_tab[CKK];                      // (c*HW + dh*56 + dw) | (t<<24), t=dh*3+dw

// -------- helpers --------
__device__ __forceinline__ uint32_t smem_u32(const void* p) {
    uint32_t a;
    asm("{ .reg .u64 t; cvta.to.shared.u64 t, %1; cvt.u32.u64 %0, t; }" : "=r"(a) : "l"(p));
    return a;
}
__device__ __forceinline__ void cp16(uint32_t dst, const void* src) {
    asm volatile("cp.async.cg.shared.global [%0], [%1], 16;" :: "r"(dst), "l"(src) : "memory");
}
__device__ __forceinline__ void ldm_x4(uint32_t* r, uint32_t addr) {
    asm volatile("ldmatrix.sync.aligned.m8n8.x4.shared.b16 {%0,%1,%2,%3}, [%4];"
        : "=r"(r[0]), "=r"(r[1]), "=r"(r[2]), "=r"(r[3]) : "r"(addr));
}
__device__ __forceinline__ void mma16(float* c, const uint32_t* a, const uint32_t* b) {
    asm volatile(
        "mma.sync.aligned.m16n8k16.row.col.f32.f16.f16.f32 "
        "{%0,%1,%2,%3}, {%4,%5,%6,%7}, {%8,%9}, {%0,%1,%2,%3};"
        : "+f"(c[0]), "+f"(c[1]), "+f"(c[2]), "+f"(c[3])
        : "r"(a[0]), "r"(a[1]), "r"(a[2]), "r"(a[3]), "r"(b[0]), "r"(b[1]));
}
__device__ __forceinline__ void sts128(uint32_t addr, const uint32_t* v) {
    asm volatile("st.shared.v4.b32 [%0], {%1,%2,%3,%4};"
        :: "r"(addr), "r"(v[0]), "r"(v[1]), "r"(v[2]), "r"(v[3]) : "memory");
}

// -------- prep kernels --------
__global__ void prep_weights(const int* __restrict__ pos, const int* __restrict__ neg) {
    int i = blockIdx.x * blockDim.x + threadIdx.x;   // input layout [k][o]
    if (i < OO * CKK) {
        int k = i / OO;
        int o = i - k * OO;
        __half h = __int2half_rn(pos[i] - neg[i]);
        g_wth[o * CKK + k] = __half_as_ushort(h);
    }
}
__global__ void prep_x(const float4* __restrict__ x) {
    int i = blockIdx.x * blockDim.x + threadIdx.x;
    if (i < BB * CHW / 4) {
        float4 v = x[i];
        __half2 a = __floats2half2_rn(v.x, v.y);
        __half2 b = __floats2half2_rn(v.z, v.w);
        uint2 o;
        o.x = *reinterpret_cast<uint32_t*>(&a);
        o.y = *reinterpret_cast<uint32_t*>(&b);
        reinterpret_cast<uint2*>(g_xh)[i] = o;
    }
}
__global__ void prep_tab() {
    int k = blockIdx.x * blockDim.x + threadIdx.x;
    if (k < CKK) {
        int c = k / 9, t = k - c * 9;
        int dh = t / 3, dw = t - dh * 3;
        g_tab[k] = (uint32_t)(c * HW + dh * WW_ + dw) | ((uint32_t)t << 24);
    }
}

// -------- main kernel --------
__global__ void __launch_bounds__(NT)
conv_mma(float* __restrict__ out) {
    extern __shared__ char sm[];
    const uint32_t smb = smem_u32(sm);
    const int tid  = threadIdx.x;
    const int bn   = blockIdx.x;       // 0..391
    const int bm   = blockIdx.y;       // 0..3
    const int lane = tid & 31, wid = tid >> 5;
    const int wm   = wid & 3;          // 32-row m strip
    const int wn   = wid >> 2;         // 64-col n strip
    const int fr   = lane >> 2, fc = lane & 3;

    // ---- gather identity: fixed pixel, 16 k's per chunk ----
    const int px  = tid & 255;
    const int khp = (tid >> 8) * 16;
    const int n   = bn * BN + px;
    const int b   = n / HW;
    const int hw  = n - b * HW;
    const int h0  = hw / WW_ - 1;
    const int w0  = hw - (h0 + 1) * WW_ - 1;
    const long xbase = (long)b * CHW + (long)h0 * WW_ + w0;
    uint32_t vm = 0;
#pragma unroll
    for (int t = 0; t < 9; t++) {
        int dh = t / 3, dw = t - dh * 3;
        if ((unsigned)(h0 + dh) < HH && (unsigned)(w0 + dw) < WW_) vm |= 1u << t;
    }

    const uint16_t* Ab = g_wth + (size_t)(bm * BM) * CKK;
    const uint32_t* tabs = reinterpret_cast<const uint32_t*>(sm + OFF_TAB);

    float acc[2][8][4];
#pragma unroll
    for (int i = 0; i < 2; i++)
#pragma unroll
        for (int j = 0; j < 8; j++)
#pragma unroll
            for (int q = 0; q < 4; q++) acc[i][j][q] = 0.f;

    // A tile cp.async: 128 rows x 32 halves (64B) = 512 x 16B
#define CPA(CH, BUF) do {                                              \
        int u = tid;                                                   \
        int row = u >> 2, seg = u & 3;                                 \
        cp16(smb + OFF_A + (BUF) * A_BYTES + row * (KPAD*2) + seg * 16,\
             Ab + (size_t)row * CKK + (CH) * BK + seg * 8);            \
    } while (0)

    uint32_t gr[8];
#define GATHER(CH) do {                                                \
        const int kb = (CH) * BK + khp;                                \
        _Pragma("unroll")                                              \
        for (int j = 0; j < 16; j++) {                                 \
            uint32_t tw = tabs[kb + j];                                \
            uint32_t tt = tw >> 24;                                    \
            long off = (long)(tw & 0xFFFFFFu);                         \
            bool ok = (vm >> tt) & 1u;                                 \
            const uint16_t* p = g_xh + (ok ? xbase + off : 0);         \
            uint32_t v = (uint32_t)(*p);                               \
            v = ok ? v : 0u;                                           \
            if (j & 1) gr[j >> 1] |= v << 16; else gr[j >> 1] = v;     \
        }                                                              \
    } while (0)

    // preload: table + A(0)
    for (int u = tid; u < CKK / 4; u += NT)
        cp16(smb + OFF_TAB + u * 16, g_tab + u * 4);
    CPA(0, 0);
    asm volatile("cp.async.commit_group;" ::: "memory");
    asm volatile("cp.async.wait_group 0;" ::: "memory");
    __syncthreads();
    GATHER(0);

    for (int ch = 0; ch < NCH; ch++) {
        const int cur = ch & 1, nxt = cur ^ 1;

        // publish B(ch)
        {
            uint32_t ba = smb + OFF_B + cur * B_BYTES + px * (KPAD*2) + khp * 2;
            sts128(ba, gr);
            sts128(ba + 16, gr + 4);
        }
        if (ch + 1 < NCH) CPA(ch + 1, nxt);
        asm volatile("cp.async.commit_group;" ::: "memory");
        asm volatile("cp.async.wait_group 1;" ::: "memory");   // A(ch) resident
        __syncthreads();                                        // B(ch) visible

        if (ch + 1 < NCH) GATHER(ch + 1);   // long-latency LDGs overlap MMA

        const uint32_t aS = smb + OFF_A + cur * A_BYTES;
        const uint32_t bS = smb + OFF_B + cur * B_BYTES;
#pragma unroll
        for (int ks = 0; ks < 2; ks++) {
            uint32_t a0[4], a1[4];
            ldm_x4(a0, aS + (wm * 32 + (lane & 15)) * (KPAD*2)
                       + (ks * 16 + (lane >> 4) * 8) * 2);
            ldm_x4(a1, aS + (wm * 32 + 16 + (lane & 15)) * (KPAD*2)
                       + (ks * 16 + (lane >> 4) * 8) * 2);
#pragma unroll
            for (int ntp = 0; ntp < 4; ntp++) {
                uint32_t bb[4];
                ldm_x4(bb, bS + (wn * 64 + ntp * 16 + ((lane >> 3) >> 1) * 8 + (lane & 7)) * (KPAD*2)
                           + (ks * 16 + ((lane >> 3) & 1) * 8) * 2);
                mma16(acc[0][2*ntp],   a0, bb);
                mma16(acc[0][2*ntp+1], a0, bb + 2);
                mma16(acc[1][2*ntp],   a1, bb);
                mma16(acc[1][2*ntp+1], a1, bb + 2);
            }
        }
        // Close the WAR window: next iteration's CPA targets A[cur], which
        // lagging warps are still reading above. (This was the R8 bug.)
        __syncthreads();
    }

    // ---- epilogue: smem transpose (stride 261) -> coalesced stores, 2 passes ----
    float* epi = reinterpret_cast<float*>(sm);
    const int colg = tid & 255, rg = tid >> 8;
    const int nn2 = bn * BN + colg;
    const int b2  = nn2 / HW, hw2 = nn2 - b2 * HW;

#pragma unroll
    for (int half = 0; half < 2; half++) {
        __syncthreads();
        if ((wm >> 1) == half) {
            const int rbase = (wm & 1) * 32;   // local row base within 64
#pragma unroll
            for (int mt = 0; mt < 2; mt++)
#pragma unroll
                for (int nt = 0; nt < 8; nt++)
#pragma unroll
                    for (int q = 0; q < 4; q++) {
                        int lr = rbase + mt * 16 + fr + (q >> 1) * 8;
                        int cc2 = wn * 64 + nt * 8 + fc * 2 + (q & 1);
                        epi[lr * EPI_STRIDE + cc2] = acc[mt][nt][q];
                    }
        }
        __syncthreads();
        size_t gbase = ((size_t)b2 * OO + bm * BM + half * 64) * HW + hw2;
#pragma unroll 8
        for (int i = 0; i < 32; i++) {
            int r = rg * 32 + i;
            out[gbase + (size_t)r * HW] = epi[r * EPI_STRIDE + colg];
        }
    }
#undef CPA
#undef GATHER
}

extern "C" void kernel_launch(void* const* d_in, const int* in_sizes, int n_in,
                              void* d_out, int out_size) {
    const float* x   = (const float*)d_in[0];
    const int*   pos = (const int*)d_in[1];
    const int*   neg = (const int*)d_in[2];
    float*       out = (float*)d_out;

    cudaFuncSetAttribute(conv_mma, cudaFuncAttributeMaxDynamicSharedMemorySize, SMEM_BYTES);

    prep_weights<<<(OO * CKK + 255) / 256, 256>>>(pos, neg);
    prep_x<<<(BB * CHW / 4 + 255) / 256, 256>>>((const float4*)x);
    prep_tab<<<(CKK + 255) / 256, 256>>>();

    dim3 grid(NPIX / BN, OO / BM);   // 392 x 4
    conv_mma<<<grid, NT, SMEM_BYTES>>>(out);
}

// round 13
// speedup vs baseline: 4.6597x; 1.0809x over previous
#include <cuda_runtime.h>
#include <cuda_fp16.h>
#include <stdint.h>

#define BB   32
#define CC   256
#define HH   56
#define WW_  56
#define OO   512
#define HW   (HH*WW_)        // 3136
#define CHW  (CC*HW)         // 802816
#define CKK  (CC*9)          // 2304
#define NPIX (BB*HW)         // 100352

#define BM 128
#define BN 256
#define BK 32
#define NCH (CKK/BK)         // 72
#define NT  512
#define STAGES 3

#define KPAD 40              // halves per smem row (32 + 8 pad) = 80 B
#define A_BYTES (BM*KPAD*2)  // 10240
#define B_BYTES (BN*KPAD*2)  // 20480
#define OFF_A   0
#define OFF_B   (STAGES*A_BYTES)             // 30720
#define SMEM_BYTES (OFF_B + STAGES*B_BYTES)  // 92160
#define EPI_STRIDE 261

// -------- static device scratch --------
__device__ __align__(16) uint16_t g_wth[OO * CKK];        // ternary weights fp16 (exact)
__device__ __align__(16) uint16_t g_xh[BB * CHW];         // x as fp16
// materialized im2col, blocked [u=k/8][n][8] so prep writes AND gemm reads are 16B-coalesced
__device__ __align__(16) uint16_t g_b2[(size_t)CKK * NPIX];  // 441 MB

// -------- helpers --------
__device__ __forceinline__ uint32_t smem_u32(const void* p) {
    uint32_t a;
    asm("{ .reg .u64 t; cvta.to.shared.u64 t, %1; cvt.u32.u64 %0, t; }" : "=r"(a) : "l"(p));
    return a;
}
__device__ __forceinline__ void cp16(uint32_t dst, const void* src) {
    asm volatile("cp.async.cg.shared.global [%0], [%1], 16;" :: "r"(dst), "l"(src) : "memory");
}
__device__ __forceinline__ void ldm_x4(uint32_t* r, uint32_t addr) {
    asm volatile("ldmatrix.sync.aligned.m8n8.x4.shared.b16 {%0,%1,%2,%3}, [%4];"
        : "=r"(r[0]), "=r"(r[1]), "=r"(r[2]), "=r"(r[3]) : "r"(addr));
}
__device__ __forceinline__ void mma16(float* c, const uint32_t* a, const uint32_t* b) {
    asm volatile(
        "mma.sync.aligned.m16n8k16.row.col.f32.f16.f16.f32 "
        "{%0,%1,%2,%3}, {%4,%5,%6,%7}, {%8,%9}, {%0,%1,%2,%3};"
        : "+f"(c[0]), "+f"(c[1]), "+f"(c[2]), "+f"(c[3])
        : "r"(a[0]), "r"(a[1]), "r"(a[2]), "r"(a[3]), "r"(b[0]), "r"(b[1]));
}

// -------- prep kernels --------
__global__ void prep_weights(const int* __restrict__ pos, const int* __restrict__ neg) {
    int i = blockIdx.x * blockDim.x + threadIdx.x;   // input layout [k][o]
    if (i < OO * CKK) {
        int k = i / OO;
        int o = i - k * OO;
        __half h = __int2half_rn(pos[i] - neg[i]);
        g_wth[o * CKK + k] = __half_as_ushort(h);
    }
}
__global__ void prep_x(const float4* __restrict__ x) {
    int i = blockIdx.x * blockDim.x + threadIdx.x;
    if (i < BB * CHW / 4) {
        float4 v = x[i];
        __half2 a = __floats2half2_rn(v.x, v.y);
        __half2 b = __floats2half2_rn(v.z, v.w);
        uint2 o;
        o.x = *reinterpret_cast<uint32_t*>(&a);
        o.y = *reinterpret_cast<uint32_t*>(&b);
        reinterpret_cast<uint2*>(g_xh)[i] = o;
    }
}
// one thread = one (u, n): 8 k's for one pixel; lanes run along n so the x
// reads are w-contiguous (coalesced) and the 16B output writes are contiguous.
__global__ void prep_im2col() {
    const int n = blockIdx.x * blockDim.x + threadIdx.x;   // pixel
    const int u = blockIdx.y;                              // k-group 0..287
    const int b  = n / HW;
    const int hw = n - b * HW;
    const int h0 = hw / WW_ - 1;
    const int w0 = hw - (h0 + 1) * WW_ - 1;
    const long xbase = (long)b * CHW + (long)h0 * WW_ + w0;
    uint32_t vm = 0;
#pragma unroll
    for (int t = 0; t < 9; t++) {
        int dh = t / 3, dw = t - dh * 3;
        if ((unsigned)(h0 + dh) < HH && (unsigned)(w0 + dw) < WW_) vm |= 1u << t;
    }
    uint32_t r[4];
#pragma unroll
    for (int j = 0; j < 8; j++) {
        int k = u * 8 + j;
        int c = k / 9, t = k - c * 9;
        int dh = t / 3, dw = t - dh * 3;
        bool ok = (vm >> t) & 1u;
        long off = (long)c * HW + dh * WW_ + dw;
        uint32_t v = (uint32_t)g_xh[ok ? xbase + off : 0];
        v = ok ? v : 0u;
        if (j & 1) r[j >> 1] |= v << 16; else r[j >> 1] = v;
    }
    *reinterpret_cast<uint4*>(g_b2 + ((size_t)u * NPIX + n) * 8) =
        *reinterpret_cast<uint4*>(r);
}

// -------- main kernel: pure GEMM, 3-stage cp.async pipeline --------
__global__ void __launch_bounds__(NT)
conv_mma(float* __restrict__ out) {
    extern __shared__ char sm[];
    const uint32_t smb = smem_u32(sm);
    const int tid  = threadIdx.x;
    const int bm   = blockIdx.x;       // 0..3   (fastest: 4 CTAs share a B tile in L2)
    const int bn   = blockIdx.y;       // 0..391
    const int lane = tid & 31, wid = tid >> 5;
    const int wm   = wid & 3;          // 32-row m strip
    const int wn   = wid >> 2;         // 64-col n strip
    const int fr   = lane >> 2, fc = lane & 3;

    const uint16_t* Ab = g_wth + (size_t)(bm * BM) * CKK;
    const int n0 = bn * BN;

    float acc[2][8][4];
#pragma unroll
    for (int i = 0; i < 2; i++)
#pragma unroll
        for (int j = 0; j < 8; j++)
#pragma unroll
            for (int q = 0; q < 4; q++) acc[i][j][q] = 0.f;

#define CPA(CH, BUF) do {                                               \
        int row = tid >> 2, seg = tid & 3;                              \
        cp16(smb + OFF_A + (BUF) * A_BYTES + row * (KPAD*2) + seg * 16, \
             Ab + (size_t)row * CKK + (CH) * BK + seg * 8);             \
    } while (0)

#define CPB(CH, BUF) do {                                               \
        _Pragma("unroll")                                               \
        for (int i = 0; i < 2; i++) {                                   \
            int unit = tid + i * 512;                                   \
            int nl = unit & 255, uu = unit >> 8;                        \
            cp16(smb + OFF_B + (BUF) * B_BYTES + nl * (KPAD*2) + uu * 16, \
                 g_b2 + ((size_t)((CH) * 4 + uu) * NPIX + n0 + nl) * 8); \
        }                                                               \
    } while (0)

    // prologue: stages 0,1 in flight
    CPA(0, 0); CPB(0, 0);
    asm volatile("cp.async.commit_group;" ::: "memory");
    CPA(1, 1); CPB(1, 1);
    asm volatile("cp.async.commit_group;" ::: "memory");

    for (int ch = 0; ch < NCH; ch++) {
        if (ch < NCH - 1) asm volatile("cp.async.wait_group 1;" ::: "memory");
        else              asm volatile("cp.async.wait_group 0;" ::: "memory");
        __syncthreads();   // stage ch resident AND all warps done reading stage ch-1

        if (ch + 2 < NCH) {   // refill (ch+2)%3 — safe: issued after the barrier
            const int nb = (ch + 2) % STAGES;
            CPA(ch + 2, nb); CPB(ch + 2, nb);
            asm volatile("cp.async.commit_group;" ::: "memory");
        }

        const int buf = ch % STAGES;
        const uint32_t aS = smb + OFF_A + buf * A_BYTES;
        const uint32_t bS = smb + OFF_B + buf * B_BYTES;
#pragma unroll
        for (int ks = 0; ks < 2; ks++) {
            uint32_t a0[4], a1[4];
            ldm_x4(a0, aS + (wm * 32 + (lane & 15)) * (KPAD*2)
                       + (ks * 16 + (lane >> 4) * 8) * 2);
            ldm_x4(a1, aS + (wm * 32 + 16 + (lane & 15)) * (KPAD*2)
                       + (ks * 16 + (lane >> 4) * 8) * 2);
#pragma unroll
            for (int ntp = 0; ntp < 4; ntp++) {
                uint32_t bb[4];
                ldm_x4(bb, bS + (wn * 64 + ntp * 16 + ((lane >> 3) >> 1) * 8 + (lane & 7)) * (KPAD*2)
                           + (ks * 16 + ((lane >> 3) & 1) * 8) * 2);
                mma16(acc[0][2*ntp],   a0, bb);
                mma16(acc[0][2*ntp+1], a0, bb + 2);
                mma16(acc[1][2*ntp],   a1, bb);
                mma16(acc[1][2*ntp+1], a1, bb + 2);
            }
        }
    }
    __syncthreads();   // mainloop reads done before smem reuse

    // ---- epilogue: smem transpose (stride 261) -> coalesced stores, 2 passes ----
    float* epi = reinterpret_cast<float*>(sm);
    const int colg = tid & 255, rg = tid >> 8;
    const int nn2 = n0 + colg;
    const int b2  = nn2 / HW, hw2 = nn2 - b2 * HW;

#pragma unroll
    for (int half = 0; half < 2; half++) {
        __syncthreads();
        if ((wm >> 1) == half) {
            const int rbase = (wm & 1) * 32;
#pragma unroll
            for (int mt = 0; mt < 2; mt++)
#pragma unroll
                for (int nt = 0; nt < 8; nt++)
#pragma unroll
                    for (int q = 0; q < 4; q++) {
                        int lr = rbase + mt * 16 + fr + (q >> 1) * 8;
                        int cc2 = wn * 64 + nt * 8 + fc * 2 + (q & 1);
                        epi[lr * EPI_STRIDE + cc2] = acc[mt][nt][q];
                    }
        }
        __syncthreads();
        size_t gbase = ((size_t)b2 * OO + bm * BM + half * 64) * HW + hw2;
#pragma unroll 8
        for (int i = 0; i < 32; i++) {
            int r = rg * 32 + i;
            out[gbase + (size_t)r * HW] = epi[r * EPI_STRIDE + colg];
        }
    }
#undef CPA
#undef CPB
}

extern "C" void kernel_launch(void* const* d_in, const int* in_sizes, int n_in,
                              void* d_out, int out_size) {
    const float* x   = (const float*)d_in[0];
    const int*   pos = (const int*)d_in[1];
    const int*   neg = (const int*)d_in[2];
    float*       out = (float*)d_out;

    cudaFuncSetAttribute(conv_mma, cudaFuncAttributeMaxDynamicSharedMemorySize, SMEM_BYTES);

    prep_weights<<<(OO * CKK + 255) / 256, 256>>>(pos, neg);
    prep_x<<<(BB * CHW / 4 + 255) / 256, 256>>>((const float4*)x);
    {
        dim3 g(NPIX / 256, CKK / 8);     // 392 x 288
        prep_im2col<<<g, 256>>>();
    }
    dim3 grid(OO / BM, NPIX / BN);       // 4 x 392 (bm fastest for B-tile L2 reuse)
    conv_mma<<<grid, NT, SMEM_BYTES>>>(out);
}

// round 17
// speedup vs baseline: 5.5032x; 1.1810x over previous
#include <cuda_runtime.h>
#include <cuda_fp16.h>
#include <stdint.h>

#define BB   32
#define CC   256
#define HH   56
#define WW_  56
#define OO   512
#define HW   (HH*WW_)        // 3136
#define CHW  (CC*HW)         // 802816
#define CKK  (CC*9)          // 2304
#define NPIX (BB*HW)         // 100352

#define BM 128
#define BN 128
#define BK 32
#define NCH (CKK/BK)         // 72
#define NT  256
#define STAGES 4

#define KPAD 40              // halves per smem row (32 + 8 pad) = 80 B
#define A_BYTES (BM*KPAD*2)  // 10240
#define B_BYTES (BN*KPAD*2)  // 10240
#define OFF_A   0
#define OFF_B   (STAGES*A_BYTES)             // 40960
#define SMEM_BYTES (OFF_B + STAGES*B_BYTES)  // 81920  (x2 CTAs = 160KB < 228KB)
#define EPI_STRIDE 132

// -------- static device scratch --------
__device__ __align__(16) uint16_t g_wth[OO * CKK];           // ternary weights fp16 (exact)
// materialized im2col, blocked [u=k/8][n][8]: prep writes and gemm reads both 16B-coalesced
__device__ __align__(16) uint16_t g_b2[(size_t)CKK * NPIX];  // 441 MB

// -------- helpers --------
__device__ __forceinline__ uint32_t smem_u32(const void* p) {
    uint32_t a;
    asm("{ .reg .u64 t; cvta.to.shared.u64 t, %1; cvt.u32.u64 %0, t; }" : "=r"(a) : "l"(p));
    return a;
}
__device__ __forceinline__ void cp16(uint32_t dst, const void* src) {
    asm volatile("cp.async.cg.shared.global [%0], [%1], 16;" :: "r"(dst), "l"(src) : "memory");
}
__device__ __forceinline__ void ldm_x4(uint32_t* r, uint32_t addr) {
    asm volatile("ldmatrix.sync.aligned.m8n8.x4.shared.b16 {%0,%1,%2,%3}, [%4];"
        : "=r"(r[0]), "=r"(r[1]), "=r"(r[2]), "=r"(r[3]) : "r"(addr));
}
__device__ __forceinline__ void mma16(float* c, const uint32_t* a, const uint32_t* b) {
    asm volatile(
        "mma.sync.aligned.m16n8k16.row.col.f32.f16.f16.f32 "
        "{%0,%1,%2,%3}, {%4,%5,%6,%7}, {%8,%9}, {%0,%1,%2,%3};"
        : "+f"(c[0]), "+f"(c[1]), "+f"(c[2]), "+f"(c[3])
        : "r"(a[0]), "r"(a[1]), "r"(a[2]), "r"(a[3]), "r"(b[0]), "r"(b[1]));
}

// -------- prep kernels --------
__global__ void prep_weights(const int* __restrict__ pos, const int* __restrict__ neg) {
    int i = blockIdx.x * blockDim.x + threadIdx.x;   // input layout [k][o]
    if (i < OO * CKK) {
        int k = i / OO;
        int o = i - k * OO;
        __half h = __int2half_rn(pos[i] - neg[i]);
        g_wth[o * CKK + k] = __half_as_ushort(h);
    }
}
// one thread = one (u, n): 8 k's for one pixel, reading f32 x directly
// (lanes along n -> w-contiguous coalesced reads; 16B contiguous writes)
__global__ void prep_im2col(const float* __restrict__ x) {
    const int n = blockIdx.x * blockDim.x + threadIdx.x;   // pixel
    const int u = blockIdx.y;                              // k-group 0..287
    const int b  = n / HW;
    const int hw = n - b * HW;
    const int h0 = hw / WW_ - 1;
    const int w0 = hw - (h0 + 1) * WW_ - 1;
    const long xbase = (long)b * CHW + (long)h0 * WW_ + w0;
    uint32_t vm = 0;
#pragma unroll
    for (int t = 0; t < 9; t++) {
        int dh = t / 3, dw = t - dh * 3;
        if ((unsigned)(h0 + dh) < HH && (unsigned)(w0 + dw) < WW_) vm |= 1u << t;
    }
    uint32_t r[4];
#pragma unroll
    for (int j = 0; j < 8; j++) {
        int k = u * 8 + j;
        int c = k / 9, t = k - c * 9;
        int dh = t / 3, dw = t - dh * 3;
        bool ok = (vm >> t) & 1u;
        float f = ok ? x[xbase + (long)c * HW + dh * WW_ + dw] : 0.f;
        __half hv = __float2half_rn(f);
        uint32_t v = (uint32_t)__half_as_ushort(hv);
        if (j & 1) r[j >> 1] |= v << 16; else r[j >> 1] = v;
    }
    *reinterpret_cast<uint4*>(g_b2 + ((size_t)u * NPIX + n) * 8) =
        *reinterpret_cast<uint4*>(r);
}

// -------- main kernel: pure GEMM, 4-stage cp.async pipeline, 2 CTAs/SM --------
__global__ void __launch_bounds__(NT, 2)
conv_mma(float* __restrict__ out) {
    extern __shared__ char sm[];
    const uint32_t smb = smem_u32(sm);
    const int tid  = threadIdx.x;
    const int bm   = blockIdx.x;       // 0..3 (fastest: CTAs share B tile in L2)
    const int bn   = blockIdx.y;       // 0..783
    const int lane = tid & 31, wid = tid >> 5;
    const int wm   = wid & 3;          // 32-row m strip (4 strips = 128)
    const int wn   = wid >> 2;         // 64-col n strip (2 strips = 128)
    const int fr   = lane >> 2, fc = lane & 3;

    const uint16_t* Ab = g_wth + (size_t)(bm * BM) * CKK;
    const int n0 = bn * BN;

    float acc[2][8][4];
#pragma unroll
    for (int i = 0; i < 2; i++)
#pragma unroll
        for (int j = 0; j < 8; j++)
#pragma unroll
            for (int q = 0; q < 4; q++) acc[i][j][q] = 0.f;

    // A tile: 128 rows x 32 halves = 512 x 16B units; 256 thr -> 2 each
#define CPA(CH, BUF) do {                                               \
        _Pragma("unroll")                                               \
        for (int i = 0; i < 2; i++) {                                   \
            int unit = tid + i * 256;                                   \
            int row = unit >> 2, seg = unit & 3;                        \
            cp16(smb + OFF_A + (BUF) * A_BYTES + row * (KPAD*2) + seg * 16, \
                 Ab + (size_t)row * CKK + (CH) * BK + seg * 8);         \
        }                                                               \
    } while (0)

    // B tile: 128 px x 4 k-groups = 512 x 16B units
#define CPB(CH, BUF) do {                                               \
        _Pragma("unroll")                                               \
        for (int i = 0; i < 2; i++) {                                   \
            int unit = tid + i * 256;                                   \
            int nl = unit & 127, uu = unit >> 7;                        \
            cp16(smb + OFF_B + (BUF) * B_BYTES + nl * (KPAD*2) + uu * 16, \
                 g_b2 + ((size_t)((CH) * 4 + uu) * NPIX + n0 + nl) * 8); \
        }                                                               \
    } while (0)

    // prologue: stages 0..2 in flight
    CPA(0, 0); CPB(0, 0);
    asm volatile("cp.async.commit_group;" ::: "memory");
    CPA(1, 1); CPB(1, 1);
    asm volatile("cp.async.commit_group;" ::: "memory");
    CPA(2, 2); CPB(2, 2);
    asm volatile("cp.async.commit_group;" ::: "memory");

    for (int ch = 0; ch < NCH; ch++) {
        if (ch < NCH - 2)      asm volatile("cp.async.wait_group 2;" ::: "memory");
        else if (ch < NCH - 1) asm volatile("cp.async.wait_group 1;" ::: "memory");
        else                   asm volatile("cp.async.wait_group 0;" ::: "memory");
        __syncthreads();   // stage ch resident; all warps past iter ch-1 reads

        if (ch + 3 < NCH) {   // refill (ch+3)%4 — issued after barrier (WAR closed)
            const int nb = (ch + 3) % STAGES;
            CPA(ch + 3, nb); CPB(ch + 3, nb);
            asm volatile("cp.async.commit_group;" ::: "memory");
        }

        const int buf = ch % STAGES;
        const uint32_t aS = smb + OFF_A + buf * A_BYTES;
        const uint32_t bS = smb + OFF_B + buf * B_BYTES;
#pragma unroll
        for (int ks = 0; ks < 2; ks++) {
            uint32_t a0[4], a1[4];
            ldm_x4(a0, aS + (wm * 32 + (lane & 15)) * (KPAD*2)
                       + (ks * 16 + (lane >> 4) * 8) * 2);
            ldm_x4(a1, aS + (wm * 32 + 16 + (lane & 15)) * (KPAD*2)
                       + (ks * 16 + (lane >> 4) * 8) * 2);
#pragma unroll
            for (int ntp = 0; ntp < 4; ntp++) {
                uint32_t bb[4];
                ldm_x4(bb, bS + (wn * 64 + ntp * 16 + ((lane >> 3) >> 1) * 8 + (lane & 7)) * (KPAD*2)
                           + (ks * 16 + ((lane >> 3) & 1) * 8) * 2);
                mma16(acc[0][2*ntp],   a0, bb);
                mma16(acc[0][2*ntp+1], a0, bb + 2);
                mma16(acc[1][2*ntp],   a1, bb);
                mma16(acc[1][2*ntp+1], a1, bb + 2);
            }
        }
    }
    __syncthreads();   // mainloop reads done before smem reuse

    // ---- epilogue: smem transpose -> coalesced 512B row stores, 2 passes ----
    float* epi = reinterpret_cast<float*>(sm);
    const int colg = tid & 127, rg = tid >> 7;
    const int nn2 = n0 + colg;
    const int b2  = nn2 / HW, hw2 = nn2 - b2 * HW;

#pragma unroll
    for (int half = 0; half < 2; half++) {
        __syncthreads();
        if ((wm >> 1) == half) {
            const int rbase = (wm & 1) * 32;
#pragma unroll
            for (int mt = 0; mt < 2; mt++)
#pragma unroll
                for (int nt = 0; nt < 8; nt++)
#pragma unroll
                    for (int q = 0; q < 4; q++) {
                        int lr = rbase + mt * 16 + fr + (q >> 1) * 8;
                        int cc2 = wn * 64 + nt * 8 + fc * 2 + (q & 1);
                        epi[lr * EPI_STRIDE + cc2] = acc[mt][nt][q];
                    }
        }
        __syncthreads();
        size_t gbase = ((size_t)b2 * OO + bm * BM + half * 64) * HW + hw2;
#pragma unroll 8
        for (int i = 0; i < 32; i++) {
            int r = rg * 32 + i;
            out[gbase + (size_t)r * HW] = epi[r * EPI_STRIDE + colg];
        }
    }
#undef CPA
#undef CPB
}

extern "C" void kernel_launch(void* const* d_in, const int* in_sizes, int n_in,
                              void* d_out, int out_size) {
    const float* x   = (const float*)d_in[0];
    const int*   pos = (const int*)d_in[1];
    const int*   neg = (const int*)d_in[2];
    float*       out = (float*)d_out;

    cudaFuncSetAttribute(conv_mma, cudaFuncAttributeMaxDynamicSharedMemorySize, SMEM_BYTES);

    prep_weights<<<(OO * CKK + 255) / 256, 256>>>(pos, neg);
    {
        dim3 g(NPIX / 256, CKK / 8);     // 392 x 288
        prep_im2col<<<g, 256>>>(x);
    }
    dim3 grid(OO / BM, NPIX / BN);       // 4 x 784 (bm fastest for B-tile L2 reuse)
    conv_mma<<<grid, NT, SMEM_BYTES>>>(out);
}